// round 1
// baseline (speedup 1.0000x reference)
#include <cuda_runtime.h>

// 8-point DCT-II basis, D[u][x] = 0.5*cos((2x+1)*u*pi/16), row 0 scaled by 1/sqrt(2).
// Literals derived in double precision then rounded (matches reference's float32 cast).
__constant__ float D8c[64] = {
  0.35355339059327373f, 0.35355339059327373f, 0.35355339059327373f, 0.35355339059327373f,
  0.35355339059327373f, 0.35355339059327373f, 0.35355339059327373f, 0.35355339059327373f,

  0.49039264020161522f, 0.41573480615127262f, 0.27778511650980114f, 0.09754516100806417f,
 -0.09754516100806417f,-0.27778511650980114f,-0.41573480615127262f,-0.49039264020161522f,

  0.46193976625564337f, 0.19134171618254492f,-0.19134171618254492f,-0.46193976625564337f,
 -0.46193976625564337f,-0.19134171618254492f, 0.19134171618254492f, 0.46193976625564337f,

  0.41573480615127262f,-0.09754516100806417f,-0.49039264020161522f,-0.27778511650980114f,
  0.27778511650980114f, 0.49039264020161522f, 0.09754516100806417f,-0.41573480615127262f,

  0.35355339059327379f,-0.35355339059327379f,-0.35355339059327379f, 0.35355339059327379f,
  0.35355339059327379f,-0.35355339059327379f,-0.35355339059327379f, 0.35355339059327379f,

  0.27778511650980114f,-0.49039264020161522f, 0.09754516100806417f, 0.41573480615127262f,
 -0.41573480615127262f,-0.09754516100806417f, 0.49039264020161522f,-0.27778511650980114f,

  0.19134171618254492f,-0.46193976625564337f, 0.46193976625564337f,-0.19134171618254492f,
 -0.19134171618254492f, 0.46193976625564337f,-0.46193976625564337f, 0.19134171618254492f,

  0.09754516100806417f,-0.27778511650980114f, 0.41573480615127262f,-0.49039264020161522f,
  0.49039264020161522f,-0.41573480615127262f, 0.27778511650980114f,-0.09754516100806417f
};

__constant__ float QYc[64] = {
  16,11,10,16,24,40,51,61,
  12,12,14,19,26,58,60,55,
  14,13,16,24,40,57,69,56,
  14,17,22,29,51,87,80,62,
  18,22,37,56,68,109,103,77,
  24,35,55,64,81,104,113,92,
  49,64,78,87,103,121,120,101,
  72,92,95,98,112,100,103,99
};
__constant__ float QCc[64] = {
  17,18,24,47,99,99,99,99,
  18,21,26,66,99,99,99,99,
  24,26,56,99,99,99,99,99,
  47,66,99,99,99,99,99,99,
  99,99,99,99,99,99,99,99,
  99,99,99,99,99,99,99,99,
  99,99,99,99,99,99,99,99,
  99,99,99,99,99,99,99,99
};

// quality 75 -> factor = (200 - 150)/100 = 0.5
#define QFACTOR 0.5f

// Tile: 16 rows x 64 cols of the full-res image.
//   Y: 2x8 = 16 blocks of 8x8 (stored with -128 offset)
//   Cb/Cr: downsampled 8x32 -> 4 blocks each (stored WITHOUT the +128/-128 round trip)
// 24 blocks * 64 = 1536 DCT elements; 512 threads -> 3 items/thread/stage.

__global__ __launch_bounds__(512) void diffjpeg_kernel(
    const float* __restrict__ x, float* __restrict__ out)
{
    __shared__ float yf[16 * 65];   // padded rows: stride 65 (conflict-free)
    __shared__ float cb8[8 * 33];   // stride 33
    __shared__ float cr8[8 * 33];
    __shared__ float t1[24 * 64];   // stage temp, t1[blk*64 + u*8 + y]
    __shared__ float Ds[64];
    __shared__ float qYs[64];
    __shared__ float qCs[64];

    const int tid = threadIdx.x;
    if (tid < 64) {
        Ds[tid]  = D8c[tid];
        qYs[tid] = QYc[tid] * QFACTOR;
        qCs[tid] = QCc[tid] * QFACTOR;
    }

    const int b  = blockIdx.z;      // batch 0..15
    const int tr = blockIdx.y;      // tile row 0..31
    const int tc = blockIdx.x;      // tile col 0..7
    const size_t plane = 512 * 512;
    const float* px = x + (size_t)b * 3 * plane + (size_t)(tr * 16) * 512 + tc * 64;
    float*       po = out + (size_t)b * 3 * plane + (size_t)(tr * 16) * 512 + tc * 64;

    const int r = tid >> 6;   // 0..7 (pair of rows 2r, 2r+1)
    const int c = tid & 63;   // 0..63

    // ---- Phase 1: load, clip, RGB->YCbCr, chroma 2x2 downsample via shfl ----
    float cbsum = 0.f, crsum = 0.f;
    #pragma unroll
    for (int dr = 0; dr < 2; ++dr) {
        const int row = 2 * r + dr;
        const size_t off = (size_t)row * 512 + c;
        float rr = px[off];
        float gg = px[plane + off];
        float bb = px[2 * plane + off];
        rr = fminf(fmaxf(rr, 0.f), 1.f) * 255.f;
        gg = fminf(fmaxf(gg, 0.f), 1.f) * 255.f;
        bb = fminf(fmaxf(bb, 0.f), 1.f) * 255.f;
        const float yv = 0.299f * rr + 0.587f * gg + 0.114f * bb;
        yf[row * 65 + c] = yv - 128.f;
        cbsum += -0.168736f * rr - 0.331264f * gg + 0.5f * bb;
        crsum +=  0.5f * rr - 0.418688f * gg - 0.081312f * bb;
    }
    // horizontal neighbor: c^1 is lane^1 in the same warp
    const float cb2 = cbsum + __shfl_xor_sync(0xffffffffu, cbsum, 1);
    const float cr2 = crsum + __shfl_xor_sync(0xffffffffu, crsum, 1);
    if ((c & 1) == 0) {
        cb8[r * 33 + (c >> 1)] = 0.25f * cb2;
        cr8[r * 33 + (c >> 1)] = 0.25f * cr2;
    }
    __syncthreads();

    // Block addressing helper (inlined per stage):
    //   blk 0..15  -> Y block (blk>>3, blk&7): base yf + (blk>>3)*8*65 + (blk&7)*8, stride 65
    //   blk 16..19 -> cb8 + (blk-16)*8, stride 33
    //   blk 20..23 -> cr8 + (blk-20)*8, stride 33

    // ---- Stage A: t1[u][y] = sum_x D[u][x] * blk[x][y] ----
    #pragma unroll
    for (int k = 0; k < 3; ++k) {
        const int item = k * 512 + tid;
        const int blk = item >> 6, e = item & 63;
        const int u = e >> 3, y = e & 7;
        const float* bp; int bs;
        if (blk < 16)      { bp = yf  + (blk >> 3) * 520 + (blk & 7) * 8; bs = 65; }
        else if (blk < 20) { bp = cb8 + (blk - 16) * 8;                   bs = 33; }
        else               { bp = cr8 + (blk - 20) * 8;                   bs = 33; }
        float s = 0.f;
        #pragma unroll
        for (int xx = 0; xx < 8; ++xx) s += Ds[u * 8 + xx] * bp[xx * bs + y];
        t1[item] = s;
    }
    __syncthreads();

    // ---- Stage B: coef[u][v] = sum_y D[v][y]*t1[u][y]; quantize; write back ----
    #pragma unroll
    for (int k = 0; k < 3; ++k) {
        const int item = k * 512 + tid;
        const int blk = item >> 6, e = item & 63;
        const int u = e >> 3, v = e & 7;
        float* bp; int bs; const float* qt;
        if (blk < 16)      { bp = yf  + (blk >> 3) * 520 + (blk & 7) * 8; bs = 65; qt = qYs; }
        else if (blk < 20) { bp = cb8 + (blk - 16) * 8;                   bs = 33; qt = qCs; }
        else               { bp = cr8 + (blk - 20) * 8;                   bs = 33; qt = qCs; }
        float s = 0.f;
        #pragma unroll
        for (int yy = 0; yy < 8; ++yy) s += Ds[v * 8 + yy] * t1[blk * 64 + u * 8 + yy];
        const float q = qt[e];
        s = rintf(s / q) * q;   // rintf = round-half-even, matches jnp.round
        bp[u * bs + v] = s;
    }
    __syncthreads();

    // ---- Stage C: w[u][y] = sum_v D[v][y] * coef[u][v] ----
    #pragma unroll
    for (int k = 0; k < 3; ++k) {
        const int item = k * 512 + tid;
        const int blk = item >> 6, e = item & 63;
        const int u = e >> 3, y = e & 7;
        const float* bp; int bs;
        if (blk < 16)      { bp = yf  + (blk >> 3) * 520 + (blk & 7) * 8; bs = 65; }
        else if (blk < 20) { bp = cb8 + (blk - 16) * 8;                   bs = 33; }
        else               { bp = cr8 + (blk - 20) * 8;                   bs = 33; }
        float s = 0.f;
        #pragma unroll
        for (int vv = 0; vv < 8; ++vv) s += Ds[vv * 8 + y] * bp[u * bs + vv];
        t1[item] = s;
    }
    __syncthreads();

    // ---- Stage D: rec[x][y] = sum_u D[u][x] * w[u][y], write back ----
    #pragma unroll
    for (int k = 0; k < 3; ++k) {
        const int item = k * 512 + tid;
        const int blk = item >> 6, e = item & 63;
        const int xx = e >> 3, y = e & 7;
        float* bp; int bs;
        if (blk < 16)      { bp = yf  + (blk >> 3) * 520 + (blk & 7) * 8; bs = 65; }
        else if (blk < 20) { bp = cb8 + (blk - 16) * 8;                   bs = 33; }
        else               { bp = cr8 + (blk - 20) * 8;                   bs = 33; }
        float s = 0.f;
        #pragma unroll
        for (int uu = 0; uu < 8; ++uu) s += Ds[uu * 8 + xx] * t1[blk * 64 + uu * 8 + y];
        bp[xx * bs + y] = s;
    }
    __syncthreads();

    // ---- Phase 7: upsample chroma (nearest), YCbCr->RGB, clip, /255, store ----
    const float cbm = cb8[r * 33 + (c >> 1)];
    const float crm = cr8[r * 33 + (c >> 1)];
    #pragma unroll
    for (int dr = 0; dr < 2; ++dr) {
        const int row = 2 * r + dr;
        const size_t off = (size_t)row * 512 + c;
        const float yv = yf[row * 65 + c] + 128.f;
        float R = yv + 1.402f * crm;
        float G = yv - 0.344136f * cbm - 0.714136f * crm;
        float B = yv + 1.772f * cbm;
        R = fminf(fmaxf(R, 0.f), 255.f) * (1.0f / 255.0f);
        G = fminf(fmaxf(G, 0.f), 255.f) * (1.0f / 255.0f);
        B = fminf(fmaxf(B, 0.f), 255.f) * (1.0f / 255.0f);
        po[off]             = R;
        po[plane + off]     = G;
        po[2 * plane + off] = B;
    }
}

extern "C" void kernel_launch(void* const* d_in, const int* in_sizes, int n_in,
                              void* d_out, int out_size)
{
    const float* x = (const float*)d_in[0];
    float* out = (float*)d_out;
    (void)in_sizes; (void)n_in; (void)out_size;
    dim3 grid(8, 32, 16);   // tile cols (512/64), tile rows (512/16), batch
    diffjpeg_kernel<<<grid, 512>>>(x, out);
}

// round 2
// speedup vs baseline: 1.9660x; 1.9660x over previous
#include <cuda_runtime.h>

// 8-point DCT-II basis as compile-time constants -> FFMA immediates after unroll.
__device__ constexpr float D8[8][8] = {
  { 0.35355339059327373f, 0.35355339059327373f, 0.35355339059327373f, 0.35355339059327373f,
    0.35355339059327373f, 0.35355339059327373f, 0.35355339059327373f, 0.35355339059327373f},
  { 0.49039264020161522f, 0.41573480615127262f, 0.27778511650980114f, 0.09754516100806417f,
   -0.09754516100806417f,-0.27778511650980114f,-0.41573480615127262f,-0.49039264020161522f},
  { 0.46193976625564337f, 0.19134171618254492f,-0.19134171618254492f,-0.46193976625564337f,
   -0.46193976625564337f,-0.19134171618254492f, 0.19134171618254492f, 0.46193976625564337f},
  { 0.41573480615127262f,-0.09754516100806417f,-0.49039264020161522f,-0.27778511650980114f,
    0.27778511650980114f, 0.49039264020161522f, 0.09754516100806417f,-0.41573480615127262f},
  { 0.35355339059327379f,-0.35355339059327379f,-0.35355339059327379f, 0.35355339059327379f,
    0.35355339059327379f,-0.35355339059327379f,-0.35355339059327379f, 0.35355339059327379f},
  { 0.27778511650980114f,-0.49039264020161522f, 0.09754516100806417f, 0.41573480615127262f,
   -0.41573480615127262f,-0.09754516100806417f, 0.49039264020161522f,-0.27778511650980114f},
  { 0.19134171618254492f,-0.46193976625564337f, 0.46193976625564337f,-0.19134171618254492f,
   -0.19134171618254492f, 0.46193976625564337f,-0.46193976625564337f, 0.19134171618254492f},
  { 0.09754516100806417f,-0.27778511650980114f, 0.41573480615127262f,-0.49039264020161522f,
    0.49039264020161522f,-0.41573480615127262f, 0.27778511650980114f,-0.09754516100806417f}
};

__constant__ float QYc[64] = {
  16,11,10,16,24,40,51,61,
  12,12,14,19,26,58,60,55,
  14,13,16,24,40,57,69,56,
  14,17,22,29,51,87,80,62,
  18,22,37,56,68,109,103,77,
  24,35,55,64,81,104,113,92,
  49,64,78,87,103,121,120,101,
  72,92,95,98,112,100,103,99
};
__constant__ float QCc[64] = {
  17,18,24,47,99,99,99,99,
  18,21,26,66,99,99,99,99,
  24,26,56,99,99,99,99,99,
  47,66,99,99,99,99,99,99,
  99,99,99,99,99,99,99,99,
  99,99,99,99,99,99,99,99,
  99,99,99,99,99,99,99,99,
  99,99,99,99,99,99,99,99
};

#define QFACTOR 0.5f

// Tile: 32 rows x 64 cols. 48 blocks of 8x8 in scratch:
//   blk 0..31  : Y blocks   (br = row>>3 in 0..3, bc = col>>3 in 0..7), blk = br*8+bc
//   blk 32..39 : Cb blocks  (16x32 downsampled), blk = 32 + cbr*4 + cbc
//   blk 40..47 : Cr blocks
// Scratch layout: s[blk*72 + x*9 + y]  (row stride 9, block stride 72)
//   -> scalar LDS/STS conflict-free in BOTH row and column orientation.

__global__ __launch_bounds__(512) void diffjpeg_kernel(
    const float* __restrict__ x, float* __restrict__ out)
{
    __shared__ float s[48 * 72];
    __shared__ float qY[64], qC[64], qYi[64], qCi[64];

    const int tid = threadIdx.x;
    if (tid < 64) {
        const float a = QYc[tid] * QFACTOR;
        const float b = QCc[tid] * QFACTOR;
        qY[tid] = a;  qYi[tid] = 1.0f / a;
        qC[tid] = b;  qCi[tid] = 1.0f / b;
    }

    const int bz = blockIdx.z;      // batch 0..15
    const int tr = blockIdx.y;      // tile row 0..15 (32 rows each)
    const int tc = blockIdx.x;      // tile col 0..7  (64 cols each)
    const size_t plane = 512 * 512;
    const float* px = x   + (size_t)bz * 3 * plane + (size_t)(tr * 32) * 512 + tc * 64;
    float*       po = out + (size_t)bz * 3 * plane + (size_t)(tr * 32) * 512 + tc * 64;

    const int r = tid >> 6;   // 0..7 : row-pair within a 16-row sub-tile
    const int c = tid & 63;   // 0..63

    // ---- Phase 1: load, clip, RGB->YCbCr, chroma 2x2 downsample ----
    #pragma unroll
    for (int sub = 0; sub < 2; ++sub) {
        float cbsum = 0.f, crsum = 0.f;
        #pragma unroll
        for (int dr = 0; dr < 2; ++dr) {
            const int row = sub * 16 + 2 * r + dr;
            const size_t off = (size_t)row * 512 + c;
            float rr = px[off];
            float gg = px[plane + off];
            float bb = px[2 * plane + off];
            rr = fminf(fmaxf(rr, 0.f), 1.f) * 255.f;
            gg = fminf(fmaxf(gg, 0.f), 1.f) * 255.f;
            bb = fminf(fmaxf(bb, 0.f), 1.f) * 255.f;
            const float yv = 0.299f * rr + 0.587f * gg + 0.114f * bb;
            const int blk = (row >> 3) * 8 + (c >> 3);
            s[blk * 72 + (row & 7) * 9 + (c & 7)] = yv - 128.f;
            cbsum += -0.168736f * rr - 0.331264f * gg + 0.5f * bb;
            crsum +=  0.5f * rr - 0.418688f * gg - 0.081312f * bb;
        }
        const float cb2 = cbsum + __shfl_xor_sync(0xffffffffu, cbsum, 1);
        const float cr2 = crsum + __shfl_xor_sync(0xffffffffu, crsum, 1);
        if ((c & 1) == 0) {
            const int crow = sub * 8 + r;       // 0..15
            const int ccol = c >> 1;            // 0..31
            const int cblk = 32 + (crow >> 3) * 4 + (ccol >> 3);
            const int eoff = (crow & 7) * 9 + (ccol & 7);
            s[cblk * 72 + eoff]       = 0.25f * cb2;   // stored WITHOUT +128
            s[(cblk + 8) * 72 + eoff] = 0.25f * cr2;
        }
    }
    __syncthreads();

    // ---- Pass A: forward DCT along y (rows). One thread per block-row. ----
    if (tid < 384) {
        const int blk = tid >> 3, xx = tid & 7;
        float* bp = s + blk * 72 + xx * 9;
        float in[8];
        #pragma unroll
        for (int j = 0; j < 8; ++j) in[j] = bp[j];
        #pragma unroll
        for (int v = 0; v < 8; ++v) {
            float t = 0.f;
            #pragma unroll
            for (int y = 0; y < 8; ++y) t += D8[v][y] * in[y];
            bp[v] = t;
        }
    }
    __syncthreads();

    // ---- Pass B: forward DCT along x + quantize + inverse DCT along x ----
    if (tid < 384) {
        const int blk = tid >> 3, v = tid & 7;
        float* bp = s + blk * 72 + v;
        const float* qt  = (blk < 32) ? qY  : qC;
        const float* qti = (blk < 32) ? qYi : qCi;
        float t[8], w[8];
        #pragma unroll
        for (int xx = 0; xx < 8; ++xx) { t[xx] = bp[xx * 9]; w[xx] = 0.f; }
        #pragma unroll
        for (int u = 0; u < 8; ++u) {
            float cf = 0.f;
            #pragma unroll
            for (int xx = 0; xx < 8; ++xx) cf += D8[u][xx] * t[xx];
            const float q = qt[u * 8 + v];
            cf = rintf(cf * qti[u * 8 + v]) * q;   // round-half-even, matches jnp.round
            #pragma unroll
            for (int xx = 0; xx < 8; ++xx) w[xx] += D8[u][xx] * cf;
        }
        #pragma unroll
        for (int xx = 0; xx < 8; ++xx) bp[xx * 9] = w[xx];
    }
    __syncthreads();

    // ---- Pass C: inverse DCT along y (rows) ----
    if (tid < 384) {
        const int blk = tid >> 3, xx = tid & 7;
        float* bp = s + blk * 72 + xx * 9;
        float w[8];
        #pragma unroll
        for (int v = 0; v < 8; ++v) w[v] = bp[v];
        #pragma unroll
        for (int y = 0; y < 8; ++y) {
            float rec = 0.f;
            #pragma unroll
            for (int v = 0; v < 8; ++v) rec += D8[v][y] * w[v];
            bp[y] = rec;
        }
    }
    __syncthreads();

    // ---- Phase out: upsample chroma, YCbCr->RGB, clip, /255, store ----
    #pragma unroll
    for (int sub = 0; sub < 2; ++sub) {
        const int crow = sub * 8 + r;
        const int ccol = c >> 1;
        const int cblk = 32 + (crow >> 3) * 4 + (ccol >> 3);
        const int eoff = (crow & 7) * 9 + (ccol & 7);
        const float cbm = s[cblk * 72 + eoff];
        const float crm = s[(cblk + 8) * 72 + eoff];
        #pragma unroll
        for (int dr = 0; dr < 2; ++dr) {
            const int row = sub * 16 + 2 * r + dr;
            const size_t off = (size_t)row * 512 + c;
            const int blk = (row >> 3) * 8 + (c >> 3);
            const float yv = s[blk * 72 + (row & 7) * 9 + (c & 7)] + 128.f;
            float R = yv + 1.402f * crm;
            float G = yv - 0.344136f * cbm - 0.714136f * crm;
            float B = yv + 1.772f * cbm;
            R = fminf(fmaxf(R, 0.f), 255.f) * (1.0f / 255.0f);
            G = fminf(fmaxf(G, 0.f), 255.f) * (1.0f / 255.0f);
            B = fminf(fmaxf(B, 0.f), 255.f) * (1.0f / 255.0f);
            po[off]             = R;
            po[plane + off]     = G;
            po[2 * plane + off] = B;
        }
    }
}

extern "C" void kernel_launch(void* const* d_in, const int* in_sizes, int n_in,
                              void* d_out, int out_size)
{
    const float* x = (const float*)d_in[0];
    float* out = (float*)d_out;
    (void)in_sizes; (void)n_in; (void)out_size;
    dim3 grid(8, 16, 16);   // tile cols (512/64), tile rows (512/32), batch
    diffjpeg_kernel<<<grid, 512>>>(x, out);
}